// round 9
// baseline (speedup 1.0000x reference)
#include <cuda_runtime.h>
#include <cstdint>

// DTL loss: inputs [M,N] f32, targets [M] i32 -> scalar f32
//   pos = inputs[r, tgt[r]]
//   hard = top-num_hard of row with target masked to -inf
//   out = mean_r( (1-pos)^2 + 0.2 * mean((1+hard)^2) )
//
// One CTA per row. Threshold prefilter (x >= 2.0, target skipped inline)
// with 1-deep software prefetch (MLP-2 at unchanged occupancy). Exact
// selection: top-3-bit split + 8-bit radix refinement + rank select;
// exact global fallback when the guard fails. Last CTA (threadfence
// reduction) folds per-row results into the scalar output — single launch.

#define THREADS  256
#define CAP      1024
#define RANK_MAX 48
#define THRESH   2.0f      // f2key(2.0f) = 0xC0000000 -> bin 6
#define DELTA    0.2
#define MAXROWS  8192

__device__ double   g_rows[MAXROWS];
__device__ unsigned g_ticket;        // zero-init; self-resets each run

__device__ __forceinline__ unsigned f2key(unsigned u) {
    // monotone map: larger float -> larger unsigned key
    return u ^ (((unsigned)((int)u >> 31)) | 0x80000000u);
}
__device__ __forceinline__ float key2f(unsigned k) {
    unsigned u = (k & 0x80000000u) ? (k ^ 0x80000000u) : ~k;
    return __uint_as_float(u);
}

__global__ void __launch_bounds__(THREADS) dtl_kernel(
    const float* __restrict__ inputs,
    const int*   __restrict__ targets,
    float* __restrict__ out,
    int m, int n, int num_hard)
{
    __shared__ unsigned candA[CAP];
    __shared__ unsigned candB[CAP];
    __shared__ unsigned hist[256];
    __shared__ int    s_cnt, s_c7, s_cnt2, s_sel, s_k, s_last;
    __shared__ double warp_sums[THREADS / 32];
    __shared__ double red[THREADS];

    const int row  = blockIdx.x;
    const int tid  = threadIdx.x;
    const int lane = tid & 31;
    const int wid  = tid >> 5;
    const float* rowp = inputs + (size_t)row * (size_t)n;
    const int tgt = targets[row];

    float pos_val = 0.0f;               // used by tid 0 only
    if (tid == 0) {
        s_cnt = 0; s_c7 = 0;
        pos_val = __ldg(rowp + tgt);
    }
    __syncthreads();

    // Alignment split: head scalars to 16B boundary, float4 body, tail.
    const int off4 = (int)(((uintptr_t)rowp >> 2) & 3u);
    int head = (4 - off4) & 3;
    if (head > n) head = n;
    const int nvec = (n - head) >> 2;
    const int nsca = n - 4 * nvec;       // head + tail scalars

    // ---------- Pass 1: prefetched stream; push values >= THRESH ----------
    {
        const float4* vp = reinterpret_cast<const float4*>(rowp + head);
        float4 cur = make_float4(0.f, 0.f, 0.f, 0.f);
        if (tid < nvec) cur = __ldg(vp + tid);
        for (int j = tid; j < nvec; j += THREADS) {
            float4 nxt = make_float4(0.f, 0.f, 0.f, 0.f);
            const int jn = j + THREADS;
            if (jn < nvec) nxt = __ldg(vp + jn);   // in flight during process
            float mx = fmaxf(fmaxf(cur.x, cur.y), fmaxf(cur.z, cur.w));
            if (mx >= THRESH) {          // rare (~9% of lanes for N(0,1))
                const int base = head + 4 * j;
                float e[4] = {cur.x, cur.y, cur.z, cur.w};
#pragma unroll
                for (int q = 0; q < 4; q++) {
                    if (e[q] >= THRESH && (base + q) != tgt) {
                        int p = atomicAdd(&s_cnt, 1);
                        if (p < CAP) {
                            unsigned key = f2key(__float_as_uint(e[q]));
                            candA[p] = key;
                            if (key >= 0xE0000000u) atomicAdd(&s_c7, 1);
                        }
                    }
                }
            }
            cur = nxt;
        }
        if (tid < nsca) {
            int col = (tid < head) ? tid : (4 * nvec + tid);
            float x = __ldg(rowp + col);
            if (x >= THRESH && col != tgt) {
                int p = atomicAdd(&s_cnt, 1);
                if (p < CAP) {
                    unsigned key = f2key(__float_as_uint(x));
                    candA[p] = key;
                    if (key >= 0xE0000000u) atomicAdd(&s_c7, 1);
                }
            }
        }
    }
    __syncthreads();

    const int c  = s_cnt;
    const int c7 = s_c7;
    double acc = 0.0;

    if (num_hard > 0 && c >= num_hard && c <= CAP) {
        // ---------- Common path: exact (top-k of negatives is in candA) ----
        const int sel = (num_hard <= c7) ? 7 : 6;
        if (tid == 0) {
            s_k    = (sel == 7) ? num_hard : (num_hard - c7);
            s_cnt2 = 0;
        }
        __syncthreads();

        // Split sweep: winners (bin > sel) summed, boundary bin compacted.
        for (int j = tid; j < c; j += THREADS) {
            unsigned key = candA[j];
            int b = (int)(key >> 29);
            if (b > sel) {
                double t = 1.0 + (double)key2f(key);
                acc += t * t;
            } else if (b == sel) {
                int p = atomicAdd(&s_cnt2, 1);
                candB[p] = key;
            }
        }
        __syncthreads();

        int cc = s_cnt2;
        // ---------- 8-bit radix refinement ----------
        unsigned* src = candB;
        unsigned* dst = candA;
        const int shifts4[4] = {21, 13, 5, 0};
        for (int pi = 0; pi < 4 && cc > RANK_MAX; pi++) {
            const int sh = shifts4[pi];
            for (int i = tid; i < 256; i += THREADS) hist[i] = 0u;
            if (tid == 0) s_cnt2 = 0;
            __syncthreads();
            for (int j = tid; j < cc; j += THREADS)
                atomicAdd(&hist[(src[j] >> sh) & 255u], 1u);
            __syncthreads();
            if (wid == 0) {
                int k = s_k;
                unsigned bins[8]; unsigned t = 0u;
#pragma unroll
                for (int i = 0; i < 8; i++) { bins[i] = hist[lane * 8 + i]; t += bins[i]; }
                unsigned s = t;
#pragma unroll
                for (int o = 1; o < 32; o <<= 1) {
                    unsigned u = __shfl_down_sync(0xffffffffu, s, o);
                    if (lane + o < 32) s += u;
                }
                unsigned above = s - t;      // count in strictly higher lanes
#pragma unroll
                for (int b = 7; b >= 0; b--) {
                    if (above < (unsigned)k && (unsigned)k <= above + bins[b]) {
                        s_sel = lane * 8 + b;
                        s_k   = k - (int)above;
                    }
                    above += bins[b];
                }
            }
            __syncthreads();
            const unsigned sel2 = (unsigned)s_sel;
            for (int j = tid; j < cc; j += THREADS) {
                unsigned key = src[j];
                unsigned d = (key >> sh) & 255u;
                if (d > sel2) {
                    double t = 1.0 + (double)key2f(key);
                    acc += t * t;
                } else if (d == sel2) {
                    int p = atomicAdd(&s_cnt2, 1);
                    dst[p] = key;
                }
            }
            __syncthreads();
            cc = s_cnt2;
            unsigned* tmp = src; src = dst; dst = tmp;
        }
        // ---------- Exact rank select (index tie-break; ties equal-valued)
        const int k = s_k;
        for (int j = tid; j < cc; j += THREADS) {
            unsigned mk = src[j];
            int r = 0;
            for (int t = 0; t < cc; t++) {
                unsigned o = src[t];
                r += (o > mk) || (o == mk && t < j);
            }
            if (r < k) {
                double t = 1.0 + (double)key2f(mk);
                acc += t * t;
            }
        }
    } else if (num_hard > 0) {
        // ---------- Exact fallback: full radix select over global row ------
        acc = 0.0;
        if (tid < 32) hist[tid] = 0u;
        __syncthreads();
        for (int col = tid; col < n; col += THREADS) {
            if (col == tgt) continue;
            unsigned key = f2key(__float_as_uint(__ldg(rowp + col)));
            atomicAdd(&hist[key >> 29], 1u);
        }
        __syncthreads();
        if (wid == 0) {
            int kk = num_hard;
            unsigned cc2 = (lane < 8) ? hist[lane] : 0u;
            unsigned s = cc2;
#pragma unroll
            for (int o = 1; o < 8; o <<= 1) {
                unsigned t = __shfl_down_sync(0xffffffffu, s, o);
                if (lane + o < 8) s += t;
            }
            unsigned above = s - cc2;
            if (lane < 8 && above < (unsigned)kk && (unsigned)kk <= s) {
                s_sel = (int)lane;
                s_k   = kk - (int)above;
            }
        }
        __syncthreads();
        unsigned pmask = 0xE0000000u;
        unsigned pval  = ((unsigned)s_sel) << 29;
        for (int col = tid; col < n; col += THREADS) {
            if (col == tgt) continue;
            unsigned key = f2key(__float_as_uint(__ldg(rowp + col)));
            if ((key >> 29) > (pval >> 29)) {
                double t = 1.0 + (double)key2f(key);
                acc += t * t;
            }
        }
        const int shifts[6] = {24, 19, 14, 9, 4, 0};
        for (int lv = 0; lv < 6; lv++) {
            const int sh = shifts[lv];
            const unsigned wmask = (lv == 5) ? 0xFu : 0x1Fu;
            if (tid < 32) hist[tid] = 0u;
            __syncthreads();
            for (int col = tid; col < n; col += THREADS) {
                if (col == tgt) continue;
                unsigned key = f2key(__float_as_uint(__ldg(rowp + col)));
                if ((key & pmask) == pval)
                    atomicAdd(&hist[(key >> sh) & wmask], 1u);
            }
            __syncthreads();
            if (wid == 0) {
                int kk = s_k;
                unsigned cc2 = hist[lane];
                unsigned s = cc2;
#pragma unroll
                for (int o = 1; o < 32; o <<= 1) {
                    unsigned t = __shfl_down_sync(0xffffffffu, s, o);
                    if (lane + o < 32) s += t;
                }
                unsigned above = s - cc2;
                if (above < (unsigned)kk && (unsigned)kk <= s) {
                    s_sel = (int)lane;
                    s_k   = kk - (int)above;
                }
            }
            __syncthreads();
            const unsigned dsel = (unsigned)s_sel;
            for (int col = tid; col < n; col += THREADS) {
                if (col == tgt) continue;
                unsigned key = f2key(__float_as_uint(__ldg(rowp + col)));
                if ((key & pmask) == pval && ((key >> sh) & wmask) > dsel) {
                    double t = 1.0 + (double)key2f(key);
                    acc += t * t;
                }
            }
            pval  |= dsel << sh;
            pmask |= wmask << sh;
            __syncthreads();
        }
        if (tid == 0) {      // remaining s_k elements equal pval exactly
            double t = 1.0 + (double)key2f(pval);
            acc += (double)s_k * t * t;
        }
    }

    // ---------- Block reduction (double) + per-row result ----------
#pragma unroll
    for (int o = 16; o > 0; o >>= 1)
        acc += __shfl_down_sync(0xffffffffu, acc, o);
    if (lane == 0) warp_sums[wid] = acc;
    __syncthreads();
    if (tid == 0) {
        double tot = 0.0;
#pragma unroll
        for (int w = 0; w < THREADS / 32; w++) tot += warp_sums[w];
        double d1 = 1.0 - (double)pos_val;
        double hard = (num_hard > 0) ? tot / (double)num_hard : 0.0;
        g_rows[row] = d1 * d1 + DELTA * hard;
        __threadfence();
        unsigned old = atomicAdd(&g_ticket, 1u);
        s_last = (old == (unsigned)(m - 1)) ? 1 : 0;
    }
    __syncthreads();

    // ---------- Last CTA: fold per-row results into the scalar ----------
    if (s_last) {
        double s = 0.0;
        for (int i = tid; i < m; i += THREADS) s += g_rows[i];
        red[tid] = s;
        __syncthreads();
#pragma unroll
        for (int off = THREADS / 2; off > 0; off >>= 1) {
            if (tid < off) red[tid] += red[tid + off];
            __syncthreads();
        }
        if (tid == 0) {
            out[0] = (float)(red[0] / (double)m);
            g_ticket = 0u;               // reset for next graph replay
        }
    }
}

extern "C" void kernel_launch(void* const* d_in, const int* in_sizes, int n_in,
                              void* d_out, int out_size) {
    const float* inputs  = (const float*)d_in[0];
    const int*   targets = (const int*)d_in[1];
    int m = in_sizes[1];                    // rows (targets count)
    int n = in_sizes[0] / m;                // cols
    int num_hard = (int)(0.01 * (double)(n - 1));   // int(R*(n-1))
    if (m > MAXROWS) m = MAXROWS;           // safety (bench m = 4096)

    dtl_kernel<<<m, THREADS>>>(inputs, targets, (float*)d_out, m, n, num_hard);
}

// round 12
// speedup vs baseline: 1.3689x; 1.3689x over previous
#include <cuda_runtime.h>
#include <cstdint>

// DTL loss: inputs [M,N] f32, targets [M] i32 -> scalar f32
//   pos = inputs[r, tgt[r]]
//   hard = top-num_hard of row with target masked to -inf
//   out = mean_r( (1-pos)^2 + 0.2 * mean((1+hard)^2) )
//
// One CTA per row. Hot loop stages whole float4 groups whose max >= 2.0
// (one predicate / one atomic / one STS.128 per group) -- per-element work
// happens in a cheap smem extraction pass. Exact top-k on raw positive
// float bits via 8-bit radix refinement + rank select; exact global
// fallback when guards fail. Fused last-CTA reduction; single launch.

#define THREADS  256
#define CAP4     512       // staged float4 groups (expect ~220)
#define CAP      1024      // extracted candidates (expect ~230)
#define RANK_MAX 48
#define THRESH   2.0f
#define DELTA    0.2
#define MAXROWS  8192

__device__ double   g_rows[MAXROWS];
__device__ unsigned g_ticket;        // zero-init; last CTA resets per run

__device__ __forceinline__ unsigned f2key(unsigned u) {
    return u ^ (((unsigned)((int)u >> 31)) | 0x80000000u);
}
__device__ __forceinline__ float key2f(unsigned k) {
    unsigned u = (k & 0x80000000u) ? (k ^ 0x80000000u) : ~k;
    return __uint_as_float(u);
}

__global__ void __launch_bounds__(THREADS) dtl_kernel(
    const float* __restrict__ inputs,
    const int*   __restrict__ targets,
    float* __restrict__ out,
    int m, int n, int num_hard)
{
    __shared__ __align__(16) float4 stage[CAP4];
    __shared__ int      sidx[CAP4];
    __shared__ unsigned candA[CAP];
    __shared__ unsigned candB[CAP];
    __shared__ unsigned hist[256];
    __shared__ int    s_c4, s_cnt, s_cnt2, s_sel, s_k, s_last;
    __shared__ double warp_sums[THREADS / 32];
    __shared__ double red[THREADS];

    const int row  = blockIdx.x;
    const int tid  = threadIdx.x;
    const int lane = tid & 31;
    const int wid  = tid >> 5;
    const float* rowp = inputs + (size_t)row * (size_t)n;
    const int tgt = targets[row];

    float pos_val = 0.0f;               // used by tid 0 only
    if (tid == 0) {
        s_c4 = 0; s_cnt = 0;
        pos_val = __ldg(rowp + tgt);
    }
    __syncthreads();

    // Alignment split: head scalars to 16B boundary, float4 body, tail.
    const int off4 = (int)(((uintptr_t)rowp >> 2) & 3u);
    int head = (4 - off4) & 3;
    if (head > n) head = n;
    const int nvec = (n - head) >> 2;
    const int nsca = n - 4 * nvec;       // head + tail scalars

    // ---------- Pass 1: stream; stage whole groups with max >= THRESH ------
    {
        const float4* vp = reinterpret_cast<const float4*>(rowp + head);
#pragma unroll 2
        for (int j = tid; j < nvec; j += THREADS) {
            float4 v = __ldg(vp + j);
            float mx = fmaxf(fmaxf(v.x, v.y), fmaxf(v.z, v.w));
            if (mx >= THRESH) {          // one short arm per qualifying group
                int p = atomicAdd(&s_c4, 1);
                if (p < CAP4) { stage[p] = v; sidx[p] = j; }
            }
        }
    }
    __syncthreads();

    // ---------- Extraction: per-element filter over staged groups (smem) ---
    {
        int c4 = min(s_c4, CAP4);
        for (int i = tid; i < c4; i += THREADS) {
            float4 v = stage[i];
            int base = head + 4 * sidx[i];
            float e[4] = {v.x, v.y, v.z, v.w};
#pragma unroll
            for (int q = 0; q < 4; q++) {
                if (e[q] >= THRESH && (base + q) != tgt) {
                    int p = atomicAdd(&s_cnt, 1);
                    if (p < CAP) candA[p] = __float_as_uint(e[q]);  // raw bits
                }
            }
        }
        // head/tail scalars (<= 6 elements)
        if (tid < nsca) {
            int col = (tid < head) ? tid : (4 * nvec + tid);
            float x = __ldg(rowp + col);
            if (x >= THRESH && col != tgt) {
                int p = atomicAdd(&s_cnt, 1);
                if (p < CAP) candA[p] = __float_as_uint(x);
            }
        }
    }
    __syncthreads();

    const bool ok = (s_c4 <= CAP4) && (s_cnt <= CAP);
    const int c = s_cnt;
    double acc = 0.0;

    if (num_hard > 0 && ok && c >= num_hard) {
        // ---------- Common path: exact top-k among candA raw-bit keys ------
        // Positive floats: raw bit order == value order.
        if (tid == 0) { s_k = num_hard; s_cnt2 = 0; }
        __syncthreads();

        int cc = c;
        unsigned* src = candA;
        unsigned* dst = candB;
        const int shifts4[4] = {24, 16, 8, 0};
        for (int pi = 0; pi < 4 && cc > RANK_MAX; pi++) {
            const int sh = shifts4[pi];
            for (int i = tid; i < 256; i += THREADS) hist[i] = 0u;
            if (tid == 0) s_cnt2 = 0;
            __syncthreads();
            for (int j = tid; j < cc; j += THREADS)
                atomicAdd(&hist[(src[j] >> sh) & 255u], 1u);
            __syncthreads();
            if (wid == 0) {
                int k = s_k;
                unsigned bins[8]; unsigned t = 0u;
#pragma unroll
                for (int i = 0; i < 8; i++) { bins[i] = hist[lane * 8 + i]; t += bins[i]; }
                unsigned s = t;
#pragma unroll
                for (int o = 1; o < 32; o <<= 1) {
                    unsigned u = __shfl_down_sync(0xffffffffu, s, o);
                    if (lane + o < 32) s += u;
                }
                unsigned above = s - t;      // count in strictly higher lanes
#pragma unroll
                for (int b = 7; b >= 0; b--) {
                    if (above < (unsigned)k && (unsigned)k <= above + bins[b]) {
                        s_sel = lane * 8 + b;
                        s_k   = k - (int)above;
                    }
                    above += bins[b];
                }
            }
            __syncthreads();
            const unsigned sel2 = (unsigned)s_sel;
            for (int j = tid; j < cc; j += THREADS) {
                unsigned key = src[j];
                unsigned d = (key >> sh) & 255u;
                if (d > sel2) {
                    double t = 1.0 + (double)__uint_as_float(key);
                    acc += t * t;
                } else if (d == sel2) {
                    int p = atomicAdd(&s_cnt2, 1);
                    dst[p] = key;
                }
            }
            __syncthreads();
            cc = s_cnt2;
            unsigned* tmp = src; src = dst; dst = tmp;
        }
        // ---------- Exact rank select (index tie-break; ties equal-valued)
        const int k = s_k;
        for (int j = tid; j < cc; j += THREADS) {
            unsigned mk = src[j];
            int r = 0;
            for (int t = 0; t < cc; t++) {
                unsigned o = src[t];
                r += (o > mk) || (o == mk && t < j);
            }
            if (r < k) {
                double t = 1.0 + (double)__uint_as_float(mk);
                acc += t * t;
            }
        }
    } else if (num_hard > 0) {
        // ---------- Exact fallback: full radix select over global row ------
        acc = 0.0;
        if (tid < 32) hist[tid] = 0u;
        __syncthreads();
        for (int col = tid; col < n; col += THREADS) {
            if (col == tgt) continue;
            unsigned key = f2key(__float_as_uint(__ldg(rowp + col)));
            atomicAdd(&hist[key >> 29], 1u);
        }
        __syncthreads();
        if (wid == 0) {
            int kk = num_hard;
            unsigned cc2 = (lane < 8) ? hist[lane] : 0u;
            unsigned s = cc2;
#pragma unroll
            for (int o = 1; o < 8; o <<= 1) {
                unsigned t = __shfl_down_sync(0xffffffffu, s, o);
                if (lane + o < 8) s += t;
            }
            unsigned above = s - cc2;
            if (lane < 8 && above < (unsigned)kk && (unsigned)kk <= s) {
                s_sel = (int)lane;
                s_k   = kk - (int)above;
            }
        }
        __syncthreads();
        unsigned pmask = 0xE0000000u;
        unsigned pval  = ((unsigned)s_sel) << 29;
        for (int col = tid; col < n; col += THREADS) {
            if (col == tgt) continue;
            unsigned key = f2key(__float_as_uint(__ldg(rowp + col)));
            if ((key >> 29) > (pval >> 29)) {
                double t = 1.0 + (double)key2f(key);
                acc += t * t;
            }
        }
        const int shifts[6] = {24, 19, 14, 9, 4, 0};
        for (int lv = 0; lv < 6; lv++) {
            const int sh = shifts[lv];
            const unsigned wmask = (lv == 5) ? 0xFu : 0x1Fu;
            if (tid < 32) hist[tid] = 0u;
            __syncthreads();
            for (int col = tid; col < n; col += THREADS) {
                if (col == tgt) continue;
                unsigned key = f2key(__float_as_uint(__ldg(rowp + col)));
                if ((key & pmask) == pval)
                    atomicAdd(&hist[(key >> sh) & wmask], 1u);
            }
            __syncthreads();
            if (wid == 0) {
                int kk = s_k;
                unsigned cc2 = hist[lane];
                unsigned s = cc2;
#pragma unroll
                for (int o = 1; o < 32; o <<= 1) {
                    unsigned t = __shfl_down_sync(0xffffffffu, s, o);
                    if (lane + o < 32) s += t;
                }
                unsigned above = s - cc2;
                if (above < (unsigned)kk && (unsigned)kk <= s) {
                    s_sel = (int)lane;
                    s_k   = kk - (int)above;
                }
            }
            __syncthreads();
            const unsigned dsel = (unsigned)s_sel;
            for (int col = tid; col < n; col += THREADS) {
                if (col == tgt) continue;
                unsigned key = f2key(__float_as_uint(__ldg(rowp + col)));
                if ((key & pmask) == pval && ((key >> sh) & wmask) > dsel) {
                    double t = 1.0 + (double)key2f(key);
                    acc += t * t;
                }
            }
            pval  |= dsel << sh;
            pmask |= wmask << sh;
            __syncthreads();
        }
        if (tid == 0) {      // remaining s_k elements equal pval exactly
            double t = 1.0 + (double)key2f(pval);
            acc += (double)s_k * t * t;
        }
    }

    // ---------- Block reduction (double) + per-row result ----------
#pragma unroll
    for (int o = 16; o > 0; o >>= 1)
        acc += __shfl_down_sync(0xffffffffu, acc, o);
    if (lane == 0) warp_sums[wid] = acc;
    __syncthreads();
    if (tid == 0) {
        double tot = 0.0;
#pragma unroll
        for (int w = 0; w < THREADS / 32; w++) tot += warp_sums[w];
        double d1 = 1.0 - (double)pos_val;
        double hard = (num_hard > 0) ? tot / (double)num_hard : 0.0;
        g_rows[row] = d1 * d1 + DELTA * hard;
        __threadfence();
        unsigned old = atomicAdd(&g_ticket, 1u);
        s_last = (old == (unsigned)(m - 1)) ? 1 : 0;
    }
    __syncthreads();

    // ---------- Last CTA: fold per-row results into the scalar ----------
    if (s_last) {
        double s = 0.0;
        for (int i = tid; i < m; i += THREADS) s += g_rows[i];
        red[tid] = s;
        __syncthreads();
#pragma unroll
        for (int off = THREADS / 2; off > 0; off >>= 1) {
            if (tid < off) red[tid] += red[tid + off];
            __syncthreads();
        }
        if (tid == 0) {
            out[0] = (float)(red[0] / (double)m);
            g_ticket = 0u;               // reset for next graph replay
        }
    }
}

extern "C" void kernel_launch(void* const* d_in, const int* in_sizes, int n_in,
                              void* d_out, int out_size) {
    const float* inputs  = (const float*)d_in[0];
    const int*   targets = (const int*)d_in[1];
    int m = in_sizes[1];                    // rows (targets count)
    int n = in_sizes[0] / m;                // cols
    int num_hard = (int)(0.01 * (double)(n - 1));   // int(R*(n-1))
    if (m > MAXROWS) m = MAXROWS;           // safety (bench m = 4096)

    dtl_kernel<<<m, THREADS>>>(inputs, targets, (float*)d_out, m, n, num_hard);
}